// round 12
// baseline (speedup 1.0000x reference)
#include <cuda_runtime.h>
#include <math.h>
#include <stdint.h>

#define NB 4
#define NC 64
#define NO 64
#define NH 128
#define NW 128
#define HW (NH*NW)

typedef unsigned long long u64;

// ---- f32x2 packed helpers (sm_100+) ---------------------------------------
__device__ __forceinline__ u64 pack2(float lo, float hi) {
    u64 r; asm("mov.b64 %0, {%1, %2};" : "=l"(r) : "f"(lo), "f"(hi)); return r;
}
__device__ __forceinline__ u64 dup2(float v) {
    u64 r; asm("mov.b64 %0, {%1, %1};" : "=l"(r) : "f"(v)); return r;
}
__device__ __forceinline__ void unpack2(u64 p, float& lo, float& hi) {
    asm("mov.b64 {%0, %1}, %2;" : "=f"(lo), "=f"(hi) : "l"(p));
}
__device__ __forceinline__ u64 ffma2(u64 a, u64 b, u64 c) {
    u64 d; asm("fma.rn.f32x2 %0, %1, %2, %3;" : "=l"(d) : "l"(a), "l"(b), "l"(c)); return d;
}
__device__ __forceinline__ u64 fmul2(u64 a, u64 b) {
    u64 d; asm("mul.rn.f32x2 %0, %1, %2;" : "=l"(d) : "l"(a), "l"(b)); return d;
}
__device__ __forceinline__ void ldg128_2(const void* p, u64& lo, u64& hi) {
    asm("ld.global.nc.v2.u64 {%0,%1}, [%2];" : "=l"(lo), "=l"(hi) : "l"(p));
}
__device__ __forceinline__ void lds128_2(unsigned addr, u64& lo, u64& hi) {
    asm("ld.shared.v2.u64 {%0,%1}, [%2];" : "=l"(lo), "=l"(hi) : "r"(addr));
}

// Scratch (static device globals — no allocation)
__device__ float g_xT[NB*16*HW*4];      // x repacked: [b][c/4][h][w][4]
__device__ float g_py[NB*9*HW];         // sample y coord per (b,k,h,w)
__device__ float g_px[NB*9*HW];         // sample x coord
__device__ float g_ms[NB*9*HW];         // sigmoid(mask)
__device__ float g_Wt[9*64*64];         // weight repacked: [k][c][o]

// ---------------------------------------------------------------------------
// Kernel P: fused prep (ONE launch).
//  blocks [0, 2048):    NCHW -> [b][c/4][h][w][4] repack (coalesced via smem)
//  blocks [2048, 2192): weight reorg (g_Wt)
//  blocks [2192, 2320): offset/mask conv (reads x NCHW directly — no
//                       dependency on the transpose blocks), writes py/px/ms.
// Dynamic smem: 9*64*28 floats (weight staging for the conv blocks).
// ---------------------------------------------------------------------------
__global__ void __launch_bounds__(256) k_prep(const float* __restrict__ x,
                                              const float* __restrict__ wgt,
                                              const float* __restrict__ omw,
                                              const float* __restrict__ om_bias) {
    extern __shared__ float wsm[];      // [tap][c][28] (conv blocks only)
    int blk = blockIdx.x;
    int t = threadIdx.x;

    if (blk < 2048) {                   // ---- transpose ----
        __shared__ float ts[64][33];
        int wc = blk & 3;
        int h  = (blk >> 2) & 127;
        int b  = blk >> 9;
        int w0 = wc * 32;
        #pragma unroll
        for (int i = 0; i < 8; i++) {
            int idx = i * 256 + t;
            int c = idx >> 5, w = idx & 31;
            ts[c][w] = x[((b*64 + c)*NH + h)*NW + w0 + w];
        }
        __syncthreads();
        #pragma unroll
        for (int i = 0; i < 8; i++) {
            int idx = i * 256 + t;
            int comp = idx & 3, w = (idx >> 2) & 31, cg = idx >> 7;
            g_xT[((((b*16 + cg)*NH + h)*NW + w0 + w) << 2) + comp] = ts[cg*4 + comp][w];
        }
        return;
    }

    if (blk < 2192) {                   // ---- weight reorg ----
        int i = (blk - 2048) * 256 + t; // 0..36863
        if (i < 9*64*64) {              // g_Wt[k][c][o] = weight[o][c][k]
            int o = i & 63, c = (i >> 6) & 63, k = i >> 12;
            g_Wt[i] = wgt[(o*64 + c)*9 + k];
        }
        return;
    }

    // ---- offset/mask conv (64 -> 27ch 3x3), reads x in NCHW ----
    // Stage om weights transposed into smem: wsm[tap][c][j(pad28)]
    for (int i = t; i < 9*64*28; i += 256) {
        int j = i % 28;
        int c = (i / 28) & 63;
        int tap = i / (28*64);
        wsm[i] = (j < 27) ? __ldg(omw + (j*64 + c)*9 + tap) : 0.f;
    }
    __syncthreads();
    unsigned wsm_u = (unsigned)__cvta_generic_to_shared(wsm);

    int lin = (blk - 2192) * 256 + t;   // 0..32767 (pixel pairs)
    int w0 = (lin & 63) * 2;
    int h  = (lin >> 6) & 127;
    int b  = lin >> 13;

    u64 acc0[14], acc1[14];             // j-pairs
    #pragma unroll
    for (int j4 = 0; j4 < 7; j4++) {
        float bv[4];
        #pragma unroll
        for (int q = 0; q < 4; q++) {
            int j = j4*4 + q;
            bv[q] = (j < 27) ? __ldg(om_bias + j) : 0.f;
        }
        acc0[j4*2]   = pack2(bv[0], bv[1]);
        acc0[j4*2+1] = pack2(bv[2], bv[3]);
        acc1[j4*2]   = acc0[j4*2];
        acc1[j4*2+1] = acc0[j4*2+1];
    }

    #pragma unroll
    for (int tap = 0; tap < 9; tap++) {
        int ny  = h + tap/3 - 1;
        int nx0 = w0 + tap%3 - 1;
        bool vy = (ny >= 0) && (ny < NH);
        bool v0 = vy && (nx0 >= 0);             // nx0 <= 127 always (w0<=126)
        bool v1 = vy && (nx0 + 1 < NW);
        const float* xrow = x + ((size_t)(b*64)*NH + ny)*NW + nx0;
        #pragma unroll 4
        for (int c = 0; c < 64; c++) {
            const float* xp = xrow + (size_t)c*HW;
            float a0 = v0 ? __ldg(xp)     : 0.f;
            float a1 = v1 ? __ldg(xp + 1) : 0.f;
            u64 a0d = dup2(a0);
            u64 a1d = dup2(a1);
            unsigned wa = wsm_u + ((tap*64 + c)*28) * 4;
            #pragma unroll
            for (int j4 = 0; j4 < 7; j4++) {
                u64 wlo, whi;
                lds128_2(wa + j4*16, wlo, whi);
                acc0[j4*2]   = ffma2(wlo, a0d, acc0[j4*2]);
                acc0[j4*2+1] = ffma2(whi, a0d, acc0[j4*2+1]);
                acc1[j4*2]   = ffma2(wlo, a1d, acc1[j4*2]);
                acc1[j4*2+1] = ffma2(whi, a1d, acc1[j4*2+1]);
            }
        }
    }

    float o0[28], o1[28];
    #pragma unroll
    for (int j4 = 0; j4 < 7; j4++) {
        unpack2(acc0[j4*2],   o0[j4*4],   o0[j4*4+1]);
        unpack2(acc0[j4*2+1], o0[j4*4+2], o0[j4*4+3]);
        unpack2(acc1[j4*2],   o1[j4*4],   o1[j4*4+1]);
        unpack2(acc1[j4*2+1], o1[j4*4+2], o1[j4*4+3]);
    }

    #pragma unroll
    for (int k = 0; k < 9; k++) {
        int off = ((b*9 + k)*NH + h)*NW + w0;
        float ky = (float)(k/3), kx = (float)(k%3);
        g_py[off]     = o0[2*k]   + ky + (float)(h - 1);
        g_py[off + 1] = o1[2*k]   + ky + (float)(h - 1);
        g_px[off]     = o0[2*k+1] + kx + (float)(w0 - 1);
        g_px[off + 1] = o1[2*k+1] + kx + (float)(w0);
        g_ms[off]     = 1.f / (1.f + expf(-o0[18+k]));
        g_ms[off + 1] = 1.f / (1.f + expf(-o1[18+k]));
    }
}

// ---------------------------------------------------------------------------
// Meta for one tap (per thread: one pixel).
// ---------------------------------------------------------------------------
struct Meta {
    u64 w00d, w01d, w10d, w11d;
    int i00, i01, i10, i11;
};
__device__ __forceinline__ Meta make_meta(int mi) {
    Meta mt;
    float py  = __ldg(g_py + mi);
    float pxx = __ldg(g_px + mi);
    float m   = __ldg(g_ms + mi);
    float y0f = floorf(py), x0f = floorf(pxx);
    float wy = py - y0f, wx = pxx - x0f;
    bool vy0 = (y0f >=  0.f) && (y0f <= 127.f);
    bool vy1 = (y0f >= -1.f) && (y0f <= 126.f);
    bool vx0 = (x0f >=  0.f) && (x0f <= 127.f);
    bool vx1 = (x0f >= -1.f) && (x0f <= 126.f);
    int iy0 = (int)fminf(fmaxf(y0f,       0.f), 127.f);
    int iy1 = (int)fminf(fmaxf(y0f + 1.f, 0.f), 127.f);
    int ix0 = (int)fminf(fmaxf(x0f,       0.f), 127.f);
    int ix1 = (int)fminf(fmaxf(x0f + 1.f, 0.f), 127.f);
    mt.w00d = dup2((1.f-wy)*(1.f-wx) * ((vy0 && vx0) ? m : 0.f));
    mt.w01d = dup2((1.f-wy)*wx       * ((vy0 && vx1) ? m : 0.f));
    mt.w10d = dup2(wy*(1.f-wx)       * ((vy1 && vx0) ? m : 0.f));
    mt.w11d = dup2(wy*wx             * ((vy1 && vx1) ? m : 0.f));
    mt.i00 = iy0*NW + ix0; mt.i01 = iy0*NW + ix1;
    mt.i10 = iy1*NW + ix0; mt.i11 = iy1*NW + ix1;
    return mt;
}

// Simple full-tap gather (prologue only).
__device__ __forceinline__ void gather_tap(const char* __restrict__ xb,
                                           int mi, int px,
                                           float* __restrict__ buf) {
    Meta mt = make_meta(mi);
    #pragma unroll 4
    for (int cg = 0; cg < 16; cg++) {
        const char* cb = xb + ((size_t)cg*HW << 4);
        u64 Alo, Ahi, Blo, Bhi, Clo, Chi, Dlo, Dhi;
        ldg128_2(cb + ((size_t)mt.i00 << 4), Alo, Ahi);
        ldg128_2(cb + ((size_t)mt.i01 << 4), Blo, Bhi);
        ldg128_2(cb + ((size_t)mt.i10 << 4), Clo, Chi);
        ldg128_2(cb + ((size_t)mt.i11 << 4), Dlo, Dhi);
        u64 vlo = ffma2(mt.w00d, Alo, ffma2(mt.w01d, Blo, ffma2(mt.w10d, Clo, fmul2(mt.w11d, Dlo))));
        u64 vhi = ffma2(mt.w00d, Ahi, ffma2(mt.w01d, Bhi, ffma2(mt.w10d, Chi, fmul2(mt.w11d, Dhi))));
        float s0, s1, s2, s3;
        unpack2(vlo, s0, s1);
        unpack2(vhi, s2, s3);
        int sb = (cg*4)*64 + px;
        buf[sb]       = s0;
        buf[sb +  64] = s1;
        buf[sb + 128] = s2;
        buf[sb + 192] = s3;
    }
}

// ---------------------------------------------------------------------------
// Kernel 2: bilinear sampling + output GEMM, chunk-interleaved pipeline.
// 64-thread CTAs, one per (b,h,half): 1024 blocks, 32KB smem, 6 CTAs/SM.
// Thread tile 8px x 8o. Per chunk q: issue next-tap corner LDGs for 2 cg,
// run 8 GEMM c-iters (covers load latency), then blend+STS.
// (R10-proven version, unchanged.)
// ---------------------------------------------------------------------------
__global__ void __launch_bounds__(64, 6) k_main(const float* __restrict__ bias,
                                                float* __restrict__ out) {
    __shared__ float ssamp[2][64*64];   // 32 KB
    unsigned smem_u = (unsigned)__cvta_generic_to_shared(ssamp);
    int t = threadIdx.x;                // 0..63
    int blk = blockIdx.x;
    int half = blk & 1;
    int h = (blk >> 1) & 127;
    int b = blk >> 8;
    int w0 = half * 64;

    int px = t;                         // gather: one pixel per thread
    int px_base = (t & 7) * 8;          // GEMM: 8 pixels
    int o_base  = (t >> 3) * 8;         // GEMM: 8 outputs

    const char* xb = (const char*)g_xT + (((size_t)(b*16))*HW << 4);
    int offm = (b*9)*HW + h*NW + w0 + px;

    u64 acc[8][4];
    u64 z = dup2(0.f);
    #pragma unroll
    for (int i = 0; i < 8; i++)
        #pragma unroll
        for (int j = 0; j < 4; j++) acc[i][j] = z;

    // prologue: gather tap 0 into buf 0
    gather_tap(xb, offm, px, ssamp[0]);
    __syncthreads();

    #pragma unroll 1
    for (int k = 0; k < 8; k++) {
        unsigned sbase = smem_u + ((k & 1) * 4096 + px_base) * 4;
        const float* wk = g_Wt + k*4096 + o_base;
        float* nbuf = ssamp[(k + 1) & 1];
        Meta mt = make_meta(offm + (k+1)*HW);   // next tap's meta

        #pragma unroll
        for (int q = 0; q < 8; q++) {
            // --- issue next-tap corner loads for cg pair (2q, 2q+1) ---
            const char* cb0 = xb + ((size_t)(2*q)*HW << 4);
            const char* cb1 = xb + ((size_t)(2*q + 1)*HW << 4);
            u64 a0lo, a0hi, b0lo, b0hi, c0lo, c0hi, d0lo, d0hi;
            u64 a1lo, a1hi, b1lo, b1hi, c1lo, c1hi, d1lo, d1hi;
            ldg128_2(cb0 + ((size_t)mt.i00 << 4), a0lo, a0hi);
            ldg128_2(cb0 + ((size_t)mt.i01 << 4), b0lo, b0hi);
            ldg128_2(cb0 + ((size_t)mt.i10 << 4), c0lo, c0hi);
            ldg128_2(cb0 + ((size_t)mt.i11 << 4), d0lo, d0hi);
            ldg128_2(cb1 + ((size_t)mt.i00 << 4), a1lo, a1hi);
            ldg128_2(cb1 + ((size_t)mt.i01 << 4), b1lo, b1hi);
            ldg128_2(cb1 + ((size_t)mt.i10 << 4), c1lo, c1hi);
            ldg128_2(cb1 + ((size_t)mt.i11 << 4), d1lo, d1hi);

            // --- GEMM 8 c-iters on current tap (covers load latency) ---
            #pragma unroll
            for (int ci = 0; ci < 8; ci++) {
                int c = q*8 + ci;
                u64 s01, s23, s45, s67;
                lds128_2(sbase + c*256,      s01, s23);
                lds128_2(sbase + c*256 + 16, s45, s67);
                u64 wpa, wpb, wpc, wpd;
                ldg128_2(wk + c*64,     wpa, wpb);
                ldg128_2(wk + c*64 + 4, wpc, wpd);
                float w_[8];
                unpack2(wpa, w_[0], w_[1]);
                unpack2(wpb, w_[2], w_[3]);
                unpack2(wpc, w_[4], w_[5]);
                unpack2(wpd, w_[6], w_[7]);
                #pragma unroll
                for (int oi = 0; oi < 8; oi++) {
                    u64 wd = dup2(w_[oi]);
                    acc[oi][0] = ffma2(wd, s01, acc[oi][0]);
                    acc[oi][1] = ffma2(wd, s23, acc[oi][1]);
                    acc[oi][2] = ffma2(wd, s45, acc[oi][2]);
                    acc[oi][3] = ffma2(wd, s67, acc[oi][3]);
                }
            }

            // --- blend + store next-tap data (loads have landed) ---
            {
                u64 vlo = ffma2(mt.w00d, a0lo, ffma2(mt.w01d, b0lo, ffma2(mt.w10d, c0lo, fmul2(mt.w11d, d0lo))));
                u64 vhi = ffma2(mt.w00d, a0hi, ffma2(mt.w01d, b0hi, ffma2(mt.w10d, c0hi, fmul2(mt.w11d, d0hi))));
                float s0, s1, s2, s3;
                unpack2(vlo, s0, s1);
                unpack2(vhi, s2, s3);
                int sb = (2*q*4)*64 + px;
                nbuf[sb]       = s0;
                nbuf[sb +  64] = s1;
                nbuf[sb + 128] = s2;
                nbuf[sb + 192] = s3;
                vlo = ffma2(mt.w00d, a1lo, ffma2(mt.w01d, b1lo, ffma2(mt.w10d, c1lo, fmul2(mt.w11d, d1lo))));
                vhi = ffma2(mt.w00d, a1hi, ffma2(mt.w01d, b1hi, ffma2(mt.w10d, c1hi, fmul2(mt.w11d, d1hi))));
                unpack2(vlo, s0, s1);
                unpack2(vhi, s2, s3);
                sb += 256;
                nbuf[sb]       = s0;
                nbuf[sb +  64] = s1;
                nbuf[sb + 128] = s2;
                nbuf[sb + 192] = s3;
            }
        }
        __syncthreads();
    }

    // Final tap (k=8): GEMM only, reads buf 0 (written during k=7).
    {
        unsigned sbase = smem_u + px_base * 4;
        const float* wk = g_Wt + 8*4096 + o_base;
        #pragma unroll 4
        for (int c = 0; c < 64; c++) {
            u64 s01, s23, s45, s67;
            lds128_2(sbase + c*256,      s01, s23);
            lds128_2(sbase + c*256 + 16, s45, s67);
            u64 wpa, wpb, wpc, wpd;
            ldg128_2(wk + c*64,     wpa, wpb);
            ldg128_2(wk + c*64 + 4, wpc, wpd);
            float w_[8];
            unpack2(wpa, w_[0], w_[1]);
            unpack2(wpb, w_[2], w_[3]);
            unpack2(wpc, w_[4], w_[5]);
            unpack2(wpd, w_[6], w_[7]);
            #pragma unroll
            for (int oi = 0; oi < 8; oi++) {
                u64 wd = dup2(w_[oi]);
                acc[oi][0] = ffma2(wd, s01, acc[oi][0]);
                acc[oi][1] = ffma2(wd, s23, acc[oi][1]);
                acc[oi][2] = ffma2(wd, s45, acc[oi][2]);
                acc[oi][3] = ffma2(wd, s67, acc[oi][3]);
            }
        }
    }

    #pragma unroll
    for (int oi = 0; oi < 8; oi++) {
        float bv = __ldg(bias + o_base + oi);
        float r[8];
        unpack2(acc[oi][0], r[0], r[1]);
        unpack2(acc[oi][1], r[2], r[3]);
        unpack2(acc[oi][2], r[4], r[5]);
        unpack2(acc[oi][3], r[6], r[7]);
        float* ob = out + (((b*64 + o_base + oi)*NH + h)*NW) + w0 + px_base;
        *(float4*)ob       = make_float4(r[0]+bv, r[1]+bv, r[2]+bv, r[3]+bv);
        *(float4*)(ob + 4) = make_float4(r[4]+bv, r[5]+bv, r[6]+bv, r[7]+bv);
    }
}

// ---------------------------------------------------------------------------
extern "C" void kernel_launch(void* const* d_in, const int* in_sizes, int n_in,
                              void* d_out, int out_size) {
    const float* x         = (const float*)d_in[0];
    const float* weight    = (const float*)d_in[1];
    const float* bias      = (const float*)d_in[2];
    const float* om_weight = (const float*)d_in[3];
    const float* om_bias   = (const float*)d_in[4];
    float* out = (float*)d_out;

    cudaFuncSetAttribute(k_prep, cudaFuncAttributeMaxDynamicSharedMemorySize, 9*64*28*4);

    k_prep<<<2320, 256, 9*64*28*4>>>(x, weight, om_weight, om_bias);
    k_main<<<1024, 64>>>(bias, out);
}

// round 13
// speedup vs baseline: 1.2273x; 1.2273x over previous
#include <cuda_runtime.h>
#include <math.h>
#include <stdint.h>

#define NB 4
#define NC 64
#define NO 64
#define NH 128
#define NW 128
#define HW (NH*NW)

typedef unsigned long long u64;

// ---- f32x2 packed helpers (sm_100+) ---------------------------------------
__device__ __forceinline__ u64 pack2(float lo, float hi) {
    u64 r; asm("mov.b64 %0, {%1, %2};" : "=l"(r) : "f"(lo), "f"(hi)); return r;
}
__device__ __forceinline__ u64 dup2(float v) {
    u64 r; asm("mov.b64 %0, {%1, %1};" : "=l"(r) : "f"(v)); return r;
}
__device__ __forceinline__ void unpack2(u64 p, float& lo, float& hi) {
    asm("mov.b64 {%0, %1}, %2;" : "=f"(lo), "=f"(hi) : "l"(p));
}
__device__ __forceinline__ u64 ffma2(u64 a, u64 b, u64 c) {
    u64 d; asm("fma.rn.f32x2 %0, %1, %2, %3;" : "=l"(d) : "l"(a), "l"(b), "l"(c)); return d;
}
__device__ __forceinline__ u64 fmul2(u64 a, u64 b) {
    u64 d; asm("mul.rn.f32x2 %0, %1, %2;" : "=l"(d) : "l"(a), "l"(b)); return d;
}
__device__ __forceinline__ void ldg128_2(const void* p, u64& lo, u64& hi) {
    asm("ld.global.nc.v2.u64 {%0,%1}, [%2];" : "=l"(lo), "=l"(hi) : "l"(p));
}
__device__ __forceinline__ void lds128_2(unsigned addr, u64& lo, u64& hi) {
    asm("ld.shared.v2.u64 {%0,%1}, [%2];" : "=l"(lo), "=l"(hi) : "r"(addr));
}

// Scratch (static device globals — no allocation)
__device__ float g_xT[NB*16*HW*4];      // x repacked: [b][c/4][h][w][4]
__device__ float g_py[NB*9*HW];         // sample y coord per (b,k,h,w)
__device__ float g_px[NB*9*HW];         // sample x coord
__device__ float g_ms[NB*9*HW];         // sigmoid(mask)
__device__ float g_Wt[9*64*64];         // weight repacked: [k][c][o]
__device__ float g_omwT[9*64*28];       // om_weight repacked: [tap][c][j(pad28)]

// ---------------------------------------------------------------------------
// Kernel P: fused prep (transpose + weight reorg).
//  blocks [0, 2048):    NCHW -> [b][c/4][h][w][4] repack
//  blocks [2048, 2192): weight reorganizations
// ---------------------------------------------------------------------------
__global__ void __launch_bounds__(256) k_prep(const float* __restrict__ x,
                                              const float* __restrict__ wgt,
                                              const float* __restrict__ omw) {
    int blk = blockIdx.x;
    int t = threadIdx.x;
    if (blk < 2048) {
        __shared__ float ts[64][33];
        int wc = blk & 3;
        int h  = (blk >> 2) & 127;
        int b  = blk >> 9;
        int w0 = wc * 32;
        #pragma unroll
        for (int i = 0; i < 8; i++) {
            int idx = i * 256 + t;
            int c = idx >> 5, w = idx & 31;
            ts[c][w] = x[((b*64 + c)*NH + h)*NW + w0 + w];
        }
        __syncthreads();
        #pragma unroll
        for (int i = 0; i < 8; i++) {
            int idx = i * 256 + t;
            int comp = idx & 3, w = (idx >> 2) & 31, cg = idx >> 7;
            g_xT[((((b*16 + cg)*NH + h)*NW + w0 + w) << 2) + comp] = ts[cg*4 + comp][w];
        }
    } else {
        int i = (blk - 2048) * 256 + t;
        if (i < 9*64*64) {              // g_Wt[k][c][o] = weight[o][c][k]
            int o = i & 63, c = (i >> 6) & 63, k = i >> 12;
            g_Wt[i] = wgt[(o*64 + c)*9 + k];
        }
        if (i < 9*64*28) {              // g_omwT[tap][c][j] = om_weight[j][c][tap]
            int j = i % 28;
            int c = (i / 28) & 63;
            int tap = i / (28*64);
            g_omwT[i] = (j < 27) ? omw[(j*64 + c)*9 + tap] : 0.f;
        }
    }
}

// ---------------------------------------------------------------------------
// Kernel 1 v2: offset/mask conv (64 -> 27ch 3x3), f32x2, smem input tile.
// 128 blocks x 256 threads. Block covers 4 rows (b, hg*4 .. hg*4+3).
// Thread: 2 adjacent px, row r = t>>6, w0 = (t&63)*2.
// cg-major loop: per cg stage 6 rows x 130 x float4 tile, then 9 taps.
// Dynamic smem: weights 64512B + tile 6*130*16B = 77 KB.
// ---------------------------------------------------------------------------
#define TILE_OFF (9*64*28)              // float index where tile starts
__global__ void __launch_bounds__(256) k_offsets(const float* __restrict__ om_bias) {
    extern __shared__ float wsm[];      // [0, TILE_OFF): weights [tap][c][28]
                                        // [TILE_OFF, +6*130*4): tile[r][x+1][4]
    float4* tile = (float4*)(wsm + TILE_OFF);
    int t = threadIdx.x;
    for (int i = t; i < 9*64*28; i += 256) wsm[i] = g_omwT[i];
    unsigned wsm_u = (unsigned)__cvta_generic_to_shared(wsm);

    int blk = blockIdx.x;               // 0..127
    int hg = blk & 31;
    int b  = blk >> 5;
    int r  = t >> 6;                    // 0..3
    int h  = hg*4 + r;
    int w0 = (t & 63) * 2;

    u64 acc0[14], acc1[14];             // j pairs for px w0, w0+1
    #pragma unroll
    for (int j4 = 0; j4 < 7; j4++) {
        float bv[4];
        #pragma unroll
        for (int q = 0; q < 4; q++) {
            int j = j4*4 + q;
            bv[q] = (j < 27) ? __ldg(om_bias + j) : 0.f;
        }
        acc0[j4*2]   = pack2(bv[0], bv[1]);
        acc0[j4*2+1] = pack2(bv[2], bv[3]);
        acc1[j4*2]   = acc0[j4*2];
        acc1[j4*2+1] = acc0[j4*2+1];
    }

    #pragma unroll 1
    for (int cg = 0; cg < 16; cg++) {
        __syncthreads();                // protect previous tile reads
        // fill tile: 6 rows (hg*4-1 .. hg*4+4) x 130 (x = -1..128)
        const float4* xcg = (const float4*)g_xT + ((size_t)(b*16 + cg))*HW;
        for (int e = t; e < 6*130; e += 256) {
            int rr = e / 130;
            int xx = e % 130 - 1;
            int gy = hg*4 - 1 + rr;
            float4 v = make_float4(0.f,0.f,0.f,0.f);
            if (gy >= 0 && gy < NH && xx >= 0 && xx < NW)
                v = __ldg(xcg + gy*NW + xx);
            tile[e] = v;
        }
        __syncthreads();

        #pragma unroll
        for (int tap = 0; tap < 9; tap++) {
            int dy = tap/3, dx = tap%3;
            float4 p0 = tile[(r + dy)*130 + (w0 + dx)];
            float4 p1 = tile[(r + dy)*130 + (w0 + dx + 1)];
            float p0a[4], p1a[4];
            *(float4*)p0a = p0; *(float4*)p1a = p1;
            #pragma unroll
            for (int ci = 0; ci < 4; ci++) {
                u64 a0d = dup2(p0a[ci]);
                u64 a1d = dup2(p1a[ci]);
                unsigned wa = wsm_u + ((tap*64 + cg*4 + ci)*28) * 4;
                #pragma unroll
                for (int j4 = 0; j4 < 7; j4++) {
                    u64 wlo, whi;
                    lds128_2(wa + j4*16, wlo, whi);
                    acc0[j4*2]   = ffma2(wlo, a0d, acc0[j4*2]);
                    acc0[j4*2+1] = ffma2(whi, a0d, acc0[j4*2+1]);
                    acc1[j4*2]   = ffma2(wlo, a1d, acc1[j4*2]);
                    acc1[j4*2+1] = ffma2(whi, a1d, acc1[j4*2+1]);
                }
            }
        }
    }

    float o0[28], o1[28];
    #pragma unroll
    for (int j4 = 0; j4 < 7; j4++) {
        unpack2(acc0[j4*2],   o0[j4*4],   o0[j4*4+1]);
        unpack2(acc0[j4*2+1], o0[j4*4+2], o0[j4*4+3]);
        unpack2(acc1[j4*2],   o1[j4*4],   o1[j4*4+1]);
        unpack2(acc1[j4*2+1], o1[j4*4+2], o1[j4*4+3]);
    }

    #pragma unroll
    for (int k = 0; k < 9; k++) {
        int off = ((b*9 + k)*NH + h)*NW + w0;
        float ky = (float)(k/3), kx = (float)(k%3);
        g_py[off]     = o0[2*k]   + ky + (float)(h - 1);
        g_py[off + 1] = o1[2*k]   + ky + (float)(h - 1);
        g_px[off]     = o0[2*k+1] + kx + (float)(w0 - 1);
        g_px[off + 1] = o1[2*k+1] + kx + (float)(w0);
        g_ms[off]     = 1.f / (1.f + expf(-o0[18+k]));
        g_ms[off + 1] = 1.f / (1.f + expf(-o1[18+k]));
    }
}

// ---------------------------------------------------------------------------
// Meta for one tap (per thread: one pixel).
// ---------------------------------------------------------------------------
struct Meta {
    u64 w00d, w01d, w10d, w11d;
    int i00, i01, i10, i11;
};
__device__ __forceinline__ Meta make_meta(int mi) {
    Meta mt;
    float py  = __ldg(g_py + mi);
    float pxx = __ldg(g_px + mi);
    float m   = __ldg(g_ms + mi);
    float y0f = floorf(py), x0f = floorf(pxx);
    float wy = py - y0f, wx = pxx - x0f;
    bool vy0 = (y0f >=  0.f) && (y0f <= 127.f);
    bool vy1 = (y0f >= -1.f) && (y0f <= 126.f);
    bool vx0 = (x0f >=  0.f) && (x0f <= 127.f);
    bool vx1 = (x0f >= -1.f) && (x0f <= 126.f);
    int iy0 = (int)fminf(fmaxf(y0f,       0.f), 127.f);
    int iy1 = (int)fminf(fmaxf(y0f + 1.f, 0.f), 127.f);
    int ix0 = (int)fminf(fmaxf(x0f,       0.f), 127.f);
    int ix1 = (int)fminf(fmaxf(x0f + 1.f, 0.f), 127.f);
    mt.w00d = dup2((1.f-wy)*(1.f-wx) * ((vy0 && vx0) ? m : 0.f));
    mt.w01d = dup2((1.f-wy)*wx       * ((vy0 && vx1) ? m : 0.f));
    mt.w10d = dup2(wy*(1.f-wx)       * ((vy1 && vx0) ? m : 0.f));
    mt.w11d = dup2(wy*wx             * ((vy1 && vx1) ? m : 0.f));
    mt.i00 = iy0*NW + ix0; mt.i01 = iy0*NW + ix1;
    mt.i10 = iy1*NW + ix0; mt.i11 = iy1*NW + ix1;
    return mt;
}

// Simple full-tap gather (prologue only).
__device__ __forceinline__ void gather_tap(const char* __restrict__ xb,
                                           int mi, int px,
                                           float* __restrict__ buf) {
    Meta mt = make_meta(mi);
    #pragma unroll 4
    for (int cg = 0; cg < 16; cg++) {
        const char* cb = xb + ((size_t)cg*HW << 4);
        u64 Alo, Ahi, Blo, Bhi, Clo, Chi, Dlo, Dhi;
        ldg128_2(cb + ((size_t)mt.i00 << 4), Alo, Ahi);
        ldg128_2(cb + ((size_t)mt.i01 << 4), Blo, Bhi);
        ldg128_2(cb + ((size_t)mt.i10 << 4), Clo, Chi);
        ldg128_2(cb + ((size_t)mt.i11 << 4), Dlo, Dhi);
        u64 vlo = ffma2(mt.w00d, Alo, ffma2(mt.w01d, Blo, ffma2(mt.w10d, Clo, fmul2(mt.w11d, Dlo))));
        u64 vhi = ffma2(mt.w00d, Ahi, ffma2(mt.w01d, Bhi, ffma2(mt.w10d, Chi, fmul2(mt.w11d, Dhi))));
        float s0, s1, s2, s3;
        unpack2(vlo, s0, s1);
        unpack2(vhi, s2, s3);
        int sb = (cg*4)*64 + px;
        buf[sb]       = s0;
        buf[sb +  64] = s1;
        buf[sb + 128] = s2;
        buf[sb + 192] = s3;
    }
}

// ---------------------------------------------------------------------------
// Kernel 2: bilinear sampling + output GEMM, chunk-interleaved pipeline.
// (R10/R12-proven version, unchanged: 1024 blocks x 64 threads, 32KB smem.)
// ---------------------------------------------------------------------------
__global__ void __launch_bounds__(64, 6) k_main(const float* __restrict__ bias,
                                                float* __restrict__ out) {
    __shared__ float ssamp[2][64*64];   // 32 KB
    unsigned smem_u = (unsigned)__cvta_generic_to_shared(ssamp);
    int t = threadIdx.x;                // 0..63
    int blk = blockIdx.x;
    int half = blk & 1;
    int h = (blk >> 1) & 127;
    int b = blk >> 8;
    int w0 = half * 64;

    int px = t;                         // gather: one pixel per thread
    int px_base = (t & 7) * 8;          // GEMM: 8 pixels
    int o_base  = (t >> 3) * 8;         // GEMM: 8 outputs

    const char* xb = (const char*)g_xT + (((size_t)(b*16))*HW << 4);
    int offm = (b*9)*HW + h*NW + w0 + px;

    u64 acc[8][4];
    u64 z = dup2(0.f);
    #pragma unroll
    for (int i = 0; i < 8; i++)
        #pragma unroll
        for (int j = 0; j < 4; j++) acc[i][j] = z;

    // prologue: gather tap 0 into buf 0
    gather_tap(xb, offm, px, ssamp[0]);
    __syncthreads();

    #pragma unroll 1
    for (int k = 0; k < 8; k++) {
        unsigned sbase = smem_u + ((k & 1) * 4096 + px_base) * 4;
        const float* wk = g_Wt + k*4096 + o_base;
        float* nbuf = ssamp[(k + 1) & 1];
        Meta mt = make_meta(offm + (k+1)*HW);   // next tap's meta

        #pragma unroll
        for (int q = 0; q < 8; q++) {
            // --- issue next-tap corner loads for cg pair (2q, 2q+1) ---
            const char* cb0 = xb + ((size_t)(2*q)*HW << 4);
            const char* cb1 = xb + ((size_t)(2*q + 1)*HW << 4);
            u64 a0lo, a0hi, b0lo, b0hi, c0lo, c0hi, d0lo, d0hi;
            u64 a1lo, a1hi, b1lo, b1hi, c1lo, c1hi, d1lo, d1hi;
            ldg128_2(cb0 + ((size_t)mt.i00 << 4), a0lo, a0hi);
            ldg128_2(cb0 + ((size_t)mt.i01 << 4), b0lo, b0hi);
            ldg128_2(cb0 + ((size_t)mt.i10 << 4), c0lo, c0hi);
            ldg128_2(cb0 + ((size_t)mt.i11 << 4), d0lo, d0hi);
            ldg128_2(cb1 + ((size_t)mt.i00 << 4), a1lo, a1hi);
            ldg128_2(cb1 + ((size_t)mt.i01 << 4), b1lo, b1hi);
            ldg128_2(cb1 + ((size_t)mt.i10 << 4), c1lo, c1hi);
            ldg128_2(cb1 + ((size_t)mt.i11 << 4), d1lo, d1hi);

            // --- GEMM 8 c-iters on current tap (covers load latency) ---
            #pragma unroll
            for (int ci = 0; ci < 8; ci++) {
                int c = q*8 + ci;
                u64 s01, s23, s45, s67;
                lds128_2(sbase + c*256,      s01, s23);
                lds128_2(sbase + c*256 + 16, s45, s67);
                u64 wpa, wpb, wpc, wpd;
                ldg128_2(wk + c*64,     wpa, wpb);
                ldg128_2(wk + c*64 + 4, wpc, wpd);
                float w_[8];
                unpack2(wpa, w_[0], w_[1]);
                unpack2(wpb, w_[2], w_[3]);
                unpack2(wpc, w_[4], w_[5]);
                unpack2(wpd, w_[6], w_[7]);
                #pragma unroll
                for (int oi = 0; oi < 8; oi++) {
                    u64 wd = dup2(w_[oi]);
                    acc[oi][0] = ffma2(wd, s01, acc[oi][0]);
                    acc[oi][1] = ffma2(wd, s23, acc[oi][1]);
                    acc[oi][2] = ffma2(wd, s45, acc[oi][2]);
                    acc[oi][3] = ffma2(wd, s67, acc[oi][3]);
                }
            }

            // --- blend + store next-tap data (loads have landed) ---
            {
                u64 vlo = ffma2(mt.w00d, a0lo, ffma2(mt.w01d, b0lo, ffma2(mt.w10d, c0lo, fmul2(mt.w11d, d0lo))));
                u64 vhi = ffma2(mt.w00d, a0hi, ffma2(mt.w01d, b0hi, ffma2(mt.w10d, c0hi, fmul2(mt.w11d, d0hi))));
                float s0, s1, s2, s3;
                unpack2(vlo, s0, s1);
                unpack2(vhi, s2, s3);
                int sb = (2*q*4)*64 + px;
                nbuf[sb]       = s0;
                nbuf[sb +  64] = s1;
                nbuf[sb + 128] = s2;
                nbuf[sb + 192] = s3;
                vlo = ffma2(mt.w00d, a1lo, ffma2(mt.w01d, b1lo, ffma2(mt.w10d, c1lo, fmul2(mt.w11d, d1lo))));
                vhi = ffma2(mt.w00d, a1hi, ffma2(mt.w01d, b1hi, ffma2(mt.w10d, c1hi, fmul2(mt.w11d, d1hi))));
                unpack2(vlo, s0, s1);
                unpack2(vhi, s2, s3);
                sb += 256;
                nbuf[sb]       = s0;
                nbuf[sb +  64] = s1;
                nbuf[sb + 128] = s2;
                nbuf[sb + 192] = s3;
            }
        }
        __syncthreads();
    }

    // Final tap (k=8): GEMM only, reads buf 0 (written during k=7).
    {
        unsigned sbase = smem_u + px_base * 4;
        const float* wk = g_Wt + 8*4096 + o_base;
        #pragma unroll 4
        for (int c = 0; c < 64; c++) {
            u64 s01, s23, s45, s67;
            lds128_2(sbase + c*256,      s01, s23);
            lds128_2(sbase + c*256 + 16, s45, s67);
            u64 wpa, wpb, wpc, wpd;
            ldg128_2(wk + c*64,     wpa, wpb);
            ldg128_2(wk + c*64 + 4, wpc, wpd);
            float w_[8];
            unpack2(wpa, w_[0], w_[1]);
            unpack2(wpb, w_[2], w_[3]);
            unpack2(wpc, w_[4], w_[5]);
            unpack2(wpd, w_[6], w_[7]);
            #pragma unroll
            for (int oi = 0; oi < 8; oi++) {
                u64 wd = dup2(w_[oi]);
                acc[oi][0] = ffma2(wd, s01, acc[oi][0]);
                acc[oi][1] = ffma2(wd, s23, acc[oi][1]);
                acc[oi][2] = ffma2(wd, s45, acc[oi][2]);
                acc[oi][3] = ffma2(wd, s67, acc[oi][3]);
            }
        }
    }

    #pragma unroll
    for (int oi = 0; oi < 8; oi++) {
        float bv = __ldg(bias + o_base + oi);
        float r[8];
        unpack2(acc[oi][0], r[0], r[1]);
        unpack2(acc[oi][1], r[2], r[3]);
        unpack2(acc[oi][2], r[4], r[5]);
        unpack2(acc[oi][3], r[6], r[7]);
        float* ob = out + (((b*64 + o_base + oi)*NH + h)*NW) + w0 + px_base;
        *(float4*)ob       = make_float4(r[0]+bv, r[1]+bv, r[2]+bv, r[3]+bv);
        *(float4*)(ob + 4) = make_float4(r[4]+bv, r[5]+bv, r[6]+bv, r[7]+bv);
    }
}

// ---------------------------------------------------------------------------
extern "C" void kernel_launch(void* const* d_in, const int* in_sizes, int n_in,
                              void* d_out, int out_size) {
    const float* x         = (const float*)d_in[0];
    const float* weight    = (const float*)d_in[1];
    const float* bias      = (const float*)d_in[2];
    const float* om_weight = (const float*)d_in[3];
    const float* om_bias   = (const float*)d_in[4];
    float* out = (float*)d_out;

    const int OFF_SMEM = (9*64*28 + 6*130*4) * 4;   // 77,632 B
    cudaFuncSetAttribute(k_offsets, cudaFuncAttributeMaxDynamicSharedMemorySize, OFF_SMEM);

    k_prep<<<2192, 256>>>(x, weight, om_weight);
    k_offsets<<<128, 256, OFF_SMEM>>>(om_bias);
    k_main<<<1024, 64>>>(bias, out);
}

// round 16
// speedup vs baseline: 1.2879x; 1.0493x over previous
#include <cuda_runtime.h>
#include <math.h>
#include <stdint.h>

#define NB 4
#define NC 64
#define NO 64
#define NH 128
#define NW 128
#define HW (NH*NW)
#define JS (4*HW)                       // j-plane stride in g_p0/g_p1

typedef unsigned long long u64;

// ---- f32x2 packed helpers (sm_100+) ---------------------------------------
__device__ __forceinline__ u64 pack2(float lo, float hi) {
    u64 r; asm("mov.b64 %0, {%1, %2};" : "=l"(r) : "f"(lo), "f"(hi)); return r;
}
__device__ __forceinline__ u64 dup2(float v) {
    u64 r; asm("mov.b64 %0, {%1, %1};" : "=l"(r) : "f"(v)); return r;
}
__device__ __forceinline__ void unpack2(u64 p, float& lo, float& hi) {
    asm("mov.b64 {%0, %1}, %2;" : "=f"(lo), "=f"(hi) : "l"(p));
}
__device__ __forceinline__ u64 ffma2(u64 a, u64 b, u64 c) {
    u64 d; asm("fma.rn.f32x2 %0, %1, %2, %3;" : "=l"(d) : "l"(a), "l"(b), "l"(c)); return d;
}
__device__ __forceinline__ u64 fmul2(u64 a, u64 b) {
    u64 d; asm("mul.rn.f32x2 %0, %1, %2;" : "=l"(d) : "l"(a), "l"(b)); return d;
}
__device__ __forceinline__ void ldg128_2(const void* p, u64& lo, u64& hi) {
    asm("ld.global.nc.v2.u64 {%0,%1}, [%2];" : "=l"(lo), "=l"(hi) : "l"(p));
}
__device__ __forceinline__ void lds128_2(unsigned addr, u64& lo, u64& hi) {
    asm("ld.shared.v2.u64 {%0,%1}, [%2];" : "=l"(lo), "=l"(hi) : "r"(addr));
}

// Scratch (static device globals — no allocation)
__device__ float g_xT[NB*16*HW*4];      // x repacked: [b][c/4][h][w][4]
__device__ float g_p0[28*NB*HW];        // offset-conv partial (channels 0-31, incl bias)
__device__ float g_p1[28*NB*HW];        // offset-conv partial (channels 32-63)
__device__ float g_Wt[9*64*64];         // weight repacked: [k][c][o]

// ---------------------------------------------------------------------------
// Kernel P: everything before the main loop, ONE launch.
//  blocks [0, 256):     offset/mask conv, split by channel half. Reads x NCHW
//                       (coalesced float4 row tiles) — independent of transpose.
//  blocks [256, 2304):  NCHW -> [b][c/4][h][w][4] repack
//  blocks [2304, 2448): weight reorg (g_Wt)
// Conv blocks come FIRST so they start immediately; the light transpose/reorg
// blocks fill remaining SM capacity around them.
// Dynamic smem (conv blocks): weights 9*32*28 + tile 4*6*132 floats = 44928 B.
// NOTE: static ts (8448B) + dynamic (44928B) = 53376B > 48KB default — the
// cudaFuncSetAttribute opt-in in kernel_launch is REQUIRED.
// ---------------------------------------------------------------------------
__global__ void __launch_bounds__(256) k_prep(const float* __restrict__ x,
                                              const float* __restrict__ wgt,
                                              const float* __restrict__ omw,
                                              const float* __restrict__ om_bias) {
    extern __shared__ float wsm[];      // conv: [tap][cl(32)][j(pad28)] then tile
    int blk = blockIdx.x;
    int t = threadIdx.x;

    if (blk >= 256) {
        if (blk < 2304) {               // ---- transpose ----
            __shared__ float ts[64][33];
            int b2 = blk - 256;
            int wc = b2 & 3;
            int h  = (b2 >> 2) & 127;
            int b  = b2 >> 9;
            int w0 = wc * 32;
            #pragma unroll
            for (int i = 0; i < 8; i++) {
                int idx = i * 256 + t;
                int c = idx >> 5, w = idx & 31;
                ts[c][w] = x[((b*64 + c)*NH + h)*NW + w0 + w];
            }
            __syncthreads();
            #pragma unroll
            for (int i = 0; i < 8; i++) {
                int idx = i * 256 + t;
                int comp = idx & 3, w = (idx >> 2) & 31, cg = idx >> 7;
                g_xT[((((b*16 + cg)*NH + h)*NW + w0 + w) << 2) + comp] = ts[cg*4 + comp][w];
            }
        } else {                        // ---- weight reorg ----
            int i = (blk - 2304) * 256 + t;
            if (i < 9*64*64) {          // g_Wt[k][c][o] = weight[o][c][k]
                int o = i & 63, c = (i >> 6) & 63, k = i >> 12;
                g_Wt[i] = wgt[(o*64 + c)*9 + k];
            }
        }
        return;
    }

    // ================= offset/mask conv, half the channels =================
    int half = blk & 1;                 // channel half: 0 -> c 0-31, 1 -> 32-63
    int g    = blk >> 1;                // 0..127
    int hg   = g & 31;
    int b    = g >> 5;
    int r    = t >> 6;                  // 0..3 (row within 4-row group)
    int h    = hg*4 + r;
    int w0c  = (t & 63) * 2;            // 2 adjacent pixels

    float* tile = wsm + 9*32*28;        // [ci][6 rows][132]

    // stage this half's om weights transposed: wsm[(tap*32+cl)*28+j]
    for (int i = t; i < 9*32*28; i += 256) {
        int j = i % 28;
        int cl = (i / 28) & 31;
        int tap = i / (28*32);
        wsm[i] = (j < 27) ? __ldg(omw + (j*64 + half*32 + cl)*9 + tap) : 0.f;
    }
    unsigned wsm_u = (unsigned)__cvta_generic_to_shared(wsm);

    u64 acc0[14], acc1[14];
    #pragma unroll
    for (int j4 = 0; j4 < 7; j4++) {
        float bv[4];
        #pragma unroll
        for (int q = 0; q < 4; q++) {
            int j = j4*4 + q;
            bv[q] = (half == 0 && j < 27) ? __ldg(om_bias + j) : 0.f;
        }
        acc0[j4*2]   = pack2(bv[0], bv[1]);
        acc0[j4*2+1] = pack2(bv[2], bv[3]);
        acc1[j4*2]   = acc0[j4*2];
        acc1[j4*2+1] = acc0[j4*2+1];
    }

    #pragma unroll 1
    for (int cgl = 0; cgl < 8; cgl++) {
        int cg = half*8 + cgl;          // global channel group
        __syncthreads();                // protect previous tile reads (+ weights on first iter)
        // fill tile: 4 channels x 6 rows x 132 slots (halo zeros in 128..131)
        for (int e = t; e < 4*6*33; e += 256) {
            int ci  = e / 198;          // 6*33
            int rem = e - ci*198;
            int rr  = rem / 33;
            int seg = rem - rr*33;
            int gy  = hg*4 - 1 + rr;
            float4 v = make_float4(0.f, 0.f, 0.f, 0.f);
            if (seg < 32 && gy >= 0 && gy < NH) {
                int c = cg*4 + ci;
                v = __ldg(((const float4*)(x + ((size_t)(b*64 + c)*NH + gy)*NW)) + seg);
            }
            *((float4*)&tile[(ci*6 + rr)*132 + seg*4]) = v;
        }
        __syncthreads();

        #pragma unroll
        for (int tap = 0; tap < 9; tap++) {
            int dy = tap/3, dx = tap%3;
            int rdy = r + dy;
            int xx0 = w0c + dx - 1;
            int slot0 = (xx0 < 0) ? 129 : xx0;   // slot 129 is a guaranteed zero
            int xx1 = xx0 + 1;
            #pragma unroll
            for (int ci = 0; ci < 4; ci++) {
                float a0 = tile[(ci*6 + rdy)*132 + slot0];
                float a1 = tile[(ci*6 + rdy)*132 + xx1];
                u64 a0d = dup2(a0);
                u64 a1d = dup2(a1);
                unsigned wa = wsm_u + ((tap*32 + cgl*4 + ci)*28) * 4;
                #pragma unroll
                for (int j4 = 0; j4 < 7; j4++) {
                    u64 wlo, whi;
                    lds128_2(wa + j4*16, wlo, whi);
                    acc0[j4*2]   = ffma2(wlo, a0d, acc0[j4*2]);
                    acc0[j4*2+1] = ffma2(whi, a0d, acc0[j4*2+1]);
                    acc1[j4*2]   = ffma2(wlo, a1d, acc1[j4*2]);
                    acc1[j4*2+1] = ffma2(whi, a1d, acc1[j4*2+1]);
                }
            }
        }
    }

    float o0[28], o1[28];
    #pragma unroll
    for (int j4 = 0; j4 < 7; j4++) {
        unpack2(acc0[j4*2],   o0[j4*4],   o0[j4*4+1]);
        unpack2(acc0[j4*2+1], o0[j4*4+2], o0[j4*4+3]);
        unpack2(acc1[j4*2],   o1[j4*4],   o1[j4*4+1]);
        unpack2(acc1[j4*2+1], o1[j4*4+2], o1[j4*4+3]);
    }

    float* dst = half ? g_p1 : g_p0;
    int base = b*HW + h*NW + w0c;
    #pragma unroll
    for (int j = 0; j < 27; j++) {
        dst[j*JS + base]     = o0[j];
        dst[j*JS + base + 1] = o1[j];
    }
}

// ---------------------------------------------------------------------------
// Meta for one tap (per thread: one pixel). Sums the two conv partials,
// applies sigmoid + base coords.
// ---------------------------------------------------------------------------
struct Meta {
    u64 w00d, w01d, w10d, w11d;
    int i00, i01, i10, i11;
};
__device__ __forceinline__ Meta make_meta(int base2, int k, int h, int gwx) {
    int js = 2*k*JS;
    float py  = __ldg(g_p0 + base2 + js)      + __ldg(g_p1 + base2 + js)
              + (float)(k/3) + (float)(h - 1);
    float pxx = __ldg(g_p0 + base2 + js + JS) + __ldg(g_p1 + base2 + js + JS)
              + (float)(k%3) + (float)(gwx - 1);
    float ms  = __ldg(g_p0 + base2 + (18+k)*JS) + __ldg(g_p1 + base2 + (18+k)*JS);
    float m   = 1.f / (1.f + expf(-ms));
    Meta mt;
    float y0f = floorf(py), x0f = floorf(pxx);
    float wy = py - y0f, wx = pxx - x0f;
    bool vy0 = (y0f >=  0.f) && (y0f <= 127.f);
    bool vy1 = (y0f >= -1.f) && (y0f <= 126.f);
    bool vx0 = (x0f >=  0.f) && (x0f <= 127.f);
    bool vx1 = (x0f >= -1.f) && (x0f <= 126.f);
    int iy0 = (int)fminf(fmaxf(y0f,       0.f), 127.f);
    int iy1 = (int)fminf(fmaxf(y0f + 1.f, 0.f), 127.f);
    int ix0 = (int)fminf(fmaxf(x0f,       0.f), 127.f);
    int ix1 = (int)fminf(fmaxf(x0f + 1.f, 0.f), 127.f);
    mt.w00d = dup2((1.f-wy)*(1.f-wx) * ((vy0 && vx0) ? m : 0.f));
    mt.w01d = dup2((1.f-wy)*wx       * ((vy0 && vx1) ? m : 0.f));
    mt.w10d = dup2(wy*(1.f-wx)       * ((vy1 && vx0) ? m : 0.f));
    mt.w11d = dup2(wy*wx             * ((vy1 && vx1) ? m : 0.f));
    mt.i00 = iy0*NW + ix0; mt.i01 = iy0*NW + ix1;
    mt.i10 = iy1*NW + ix0; mt.i11 = iy1*NW + ix1;
    return mt;
}

// Simple full-tap gather (prologue only).
__device__ __forceinline__ void gather_tap(const char* __restrict__ xb,
                                           Meta mt, int px,
                                           float* __restrict__ buf) {
    #pragma unroll 4
    for (int cg = 0; cg < 16; cg++) {
        const char* cb = xb + ((size_t)cg*HW << 4);
        u64 Alo, Ahi, Blo, Bhi, Clo, Chi, Dlo, Dhi;
        ldg128_2(cb + ((size_t)mt.i00 << 4), Alo, Ahi);
        ldg128_2(cb + ((size_t)mt.i01 << 4), Blo, Bhi);
        ldg128_2(cb + ((size_t)mt.i10 << 4), Clo, Chi);
        ldg128_2(cb + ((size_t)mt.i11 << 4), Dlo, Dhi);
        u64 vlo = ffma2(mt.w00d, Alo, ffma2(mt.w01d, Blo, ffma2(mt.w10d, Clo, fmul2(mt.w11d, Dlo))));
        u64 vhi = ffma2(mt.w00d, Ahi, ffma2(mt.w01d, Bhi, ffma2(mt.w10d, Chi, fmul2(mt.w11d, Dhi))));
        float s0, s1, s2, s3;
        unpack2(vlo, s0, s1);
        unpack2(vhi, s2, s3);
        int sb = (cg*4)*64 + px;
        buf[sb]       = s0;
        buf[sb +  64] = s1;
        buf[sb + 128] = s2;
        buf[sb + 192] = s3;
    }
}

// ---------------------------------------------------------------------------
// Kernel 2: bilinear sampling + output GEMM, chunk-interleaved pipeline.
// (R10/R12-proven structure; only the meta source changed.)
// 1024 blocks x 64 threads, 32KB smem.
// ---------------------------------------------------------------------------
__global__ void __launch_bounds__(64, 6) k_main(const float* __restrict__ bias,
                                                float* __restrict__ out) {
    __shared__ float ssamp[2][64*64];   // 32 KB
    unsigned smem_u = (unsigned)__cvta_generic_to_shared(ssamp);
    int t = threadIdx.x;                // 0..63
    int blk = blockIdx.x;
    int half = blk & 1;
    int h = (blk >> 1) & 127;
    int b = blk >> 8;
    int w0 = half * 64;

    int px = t;                         // gather: one pixel per thread
    int gwx = w0 + px;
    int px_base = (t & 7) * 8;          // GEMM: 8 pixels
    int o_base  = (t >> 3) * 8;         // GEMM: 8 outputs

    const char* xb = (const char*)g_xT + (((size_t)(b*16))*HW << 4);
    int base2 = b*HW + h*NW + gwx;

    u64 acc[8][4];
    u64 z = dup2(0.f);
    #pragma unroll
    for (int i = 0; i < 8; i++)
        #pragma unroll
        for (int j = 0; j < 4; j++) acc[i][j] = z;

    // prologue: gather tap 0 into buf 0
    gather_tap(xb, make_meta(base2, 0, h, gwx), px, ssamp[0]);
    __syncthreads();

    #pragma unroll 1
    for (int k = 0; k < 8; k++) {
        unsigned sbase = smem_u + ((k & 1) * 4096 + px_base) * 4;
        const float* wk = g_Wt + k*4096 + o_base;
        float* nbuf = ssamp[(k + 1) & 1];
        Meta mt = make_meta(base2, k + 1, h, gwx);   // next tap's meta

        #pragma unroll
        for (int q = 0; q < 8; q++) {
            // --- issue next-tap corner loads for cg pair (2q, 2q+1) ---
            const char* cb0 = xb + ((size_t)(2*q)*HW << 4);
            const char* cb1 = xb + ((size_t)(2*q + 1)*HW << 4);
            u64 a0lo, a0hi, b0lo, b0hi, c0lo, c0hi, d0lo, d0hi;
            u64 a1lo, a1hi, b1lo, b1hi, c1lo, c1hi, d1lo, d1hi;
            ldg128_2(cb0 + ((size_t)mt.i00 << 4), a0lo, a0hi);
            ldg128_2(cb0 + ((size_t)mt.i01 << 4), b0lo, b0hi);
            ldg128_2(cb0 + ((size_t)mt.i10 << 4), c0lo, c0hi);
            ldg128_2(cb0 + ((size_t)mt.i11 << 4), d0lo, d0hi);
            ldg128_2(cb1 + ((size_t)mt.i00 << 4), a1lo, a1hi);
            ldg128_2(cb1 + ((size_t)mt.i01 << 4), b1lo, b1hi);
            ldg128_2(cb1 + ((size_t)mt.i10 << 4), c1lo, c1hi);
            ldg128_2(cb1 + ((size_t)mt.i11 << 4), d1lo, d1hi);

            // --- GEMM 8 c-iters on current tap (covers load latency) ---
            #pragma unroll
            for (int ci = 0; ci < 8; ci++) {
                int c = q*8 + ci;
                u64 s01, s23, s45, s67;
                lds128_2(sbase + c*256,      s01, s23);
                lds128_2(sbase + c*256 + 16, s45, s67);
                u64 wpa, wpb, wpc, wpd;
                ldg128_2(wk + c*64,     wpa, wpb);
                ldg128_2(wk + c*64 + 4, wpc, wpd);
                float w_[8];
                unpack2(wpa, w_[0], w_[1]);
                unpack2(wpb, w_[2], w_[3]);
                unpack2(wpc, w_[4], w_[5]);
                unpack2(wpd, w_[6], w_[7]);
                #pragma unroll
                for (int oi = 0; oi < 8; oi++) {
                    u64 wd = dup2(w_[oi]);
                    acc[oi][0] = ffma2(wd, s01, acc[oi][0]);
                    acc[oi][1] = ffma2(wd, s23, acc[oi][1]);
                    acc[oi][2] = ffma2(wd, s45, acc[oi][2]);
                    acc[oi][3] = ffma2(wd, s67, acc[oi][3]);
                }
            }

            // --- blend + store next-tap data (loads have landed) ---
            {
                u64 vlo = ffma2(mt.w00d, a0lo, ffma2(mt.w01d, b0lo, ffma2(mt.w10d, c0lo, fmul2(mt.w11d, d0lo))));
                u64 vhi = ffma2(mt.w00d, a0hi, ffma2(mt.w01d, b0hi, ffma2(mt.w10d, c0hi, fmul2(mt.w11d, d0hi))));
                float s0, s1, s2, s3;
                unpack2(vlo, s0, s1);
                unpack2(vhi, s2, s3);
                int sb = (2*q*4)*64 + px;
                nbuf[sb]       = s0;
                nbuf[sb +  64] = s1;
                nbuf[sb + 128] = s2;
                nbuf[sb + 192] = s3;
                vlo = ffma2(mt.w00d, a1lo, ffma2(mt.w01d, b1lo, ffma2(mt.w10d, c1lo, fmul2(mt.w11d, d1lo))));
                vhi = ffma2(mt.w00d, a1hi, ffma2(mt.w01d, b1hi, ffma2(mt.w10d, c1hi, fmul2(mt.w11d, d1hi))));
                unpack2(vlo, s0, s1);
                unpack2(vhi, s2, s3);
                sb += 256;
                nbuf[sb]       = s0;
                nbuf[sb +  64] = s1;
                nbuf[sb + 128] = s2;
                nbuf[sb + 192] = s3;
            }
        }
        __syncthreads();
    }

    // Final tap (k=8): GEMM only, reads buf 0 (written during k=7).
    {
        unsigned sbase = smem_u + px_base * 4;
        const float* wk = g_Wt + 8*4096 + o_base;
        #pragma unroll 4
        for (int c = 0; c < 64; c++) {
            u64 s01, s23, s45, s67;
            lds128_2(sbase + c*256,      s01, s23);
            lds128_2(sbase + c*256 + 16, s45, s67);
            u64 wpa, wpb, wpc, wpd;
            ldg128_2(wk + c*64,     wpa, wpb);
            ldg128_2(wk + c*64 + 4, wpc, wpd);
            float w_[8];
            unpack2(wpa, w_[0], w_[1]);
            unpack2(wpb, w_[2], w_[3]);
            unpack2(wpc, w_[4], w_[5]);
            unpack2(wpd, w_[6], w_[7]);
            #pragma unroll
            for (int oi = 0; oi < 8; oi++) {
                u64 wd = dup2(w_[oi]);
                acc[oi][0] = ffma2(wd, s01, acc[oi][0]);
                acc[oi][1] = ffma2(wd, s23, acc[oi][1]);
                acc[oi][2] = ffma2(wd, s45, acc[oi][2]);
                acc[oi][3] = ffma2(wd, s67, acc[oi][3]);
            }
        }
    }

    #pragma unroll
    for (int oi = 0; oi < 8; oi++) {
        float bv = __ldg(bias + o_base + oi);
        float r[8];
        unpack2(acc[oi][0], r[0], r[1]);
        unpack2(acc[oi][1], r[2], r[3]);
        unpack2(acc[oi][2], r[4], r[5]);
        unpack2(acc[oi][3], r[6], r[7]);
        float* ob = out + (((b*64 + o_base + oi)*NH + h)*NW) + w0 + px_base;
        *(float4*)ob       = make_float4(r[0]+bv, r[1]+bv, r[2]+bv, r[3]+bv);
        *(float4*)(ob + 4) = make_float4(r[4]+bv, r[5]+bv, r[6]+bv, r[7]+bv);
    }
}

// ---------------------------------------------------------------------------
extern "C" void kernel_launch(void* const* d_in, const int* in_sizes, int n_in,
                              void* d_out, int out_size) {
    const float* x         = (const float*)d_in[0];
    const float* weight    = (const float*)d_in[1];
    const float* bias      = (const float*)d_in[2];
    const float* om_weight = (const float*)d_in[3];
    const float* om_bias   = (const float*)d_in[4];
    float* out = (float*)d_out;

    const int PREP_SMEM = (9*32*28 + 4*6*132) * 4;   // 44,928 B dynamic
    // Static ts (8448B) + dynamic (44928B) > 48KB default: opt-in required.
    cudaFuncSetAttribute(k_prep, cudaFuncAttributeMaxDynamicSharedMemorySize, PREP_SMEM);

    k_prep<<<2448, 256, PREP_SMEM>>>(x, weight, om_weight, om_bias);
    k_main<<<1024, 64>>>(bias, out);
}